// round 16
// baseline (speedup 1.0000x reference)
#include <cuda_runtime.h>
#include <cstdint>

// LSTM: B x T x I -> last hidden -> FC.  I=4, H=8, O=1, T=512.
// Round-16: wall = 512 x L (serial step latency); L(224) >> static chain
// (~110) -> suspect round-robin arbitration with the co-resident warp
// stretching the chain. Fix: 512 warps (<=1/SMSP) each running TWO
// independent 8-batch chains (ILP fills latency gaps inside the warp,
// no arbiter). Plus chain algebra:
//   * h' = 2h published: h' = fma(to,tc,tc); x0.5 folded into W_hh & W_fc.
//   * c  = 0.5*fma(tf,c,c) + 0.5*fma(ti,g,g)  (sigmoid affines off-chain).
// Tail chain ~68 -> ~44 cyc. All rescalings exact (powers of 2).
// Kept: k8 MMA + C-operand IP, f16-D == A-frag identity, fp16 c.

#define T_SEQ 512
#define IDIM  4
#define HDIM  8

__device__ __forceinline__ uint32_t cvt_f16x2(float hi, float lo) {
    uint32_t r; asm("cvt.rn.f16x2.f32 %0, %1, %2;" : "=r"(r) : "f"(hi), "f"(lo)); return r;
}
__device__ __forceinline__ uint32_t htanh2(uint32_t a) {
    uint32_t d; asm("tanh.approx.f16x2 %0,%1;" : "=r"(d) : "r"(a)); return d;
}
__device__ __forceinline__ uint32_t hfma2(uint32_t a, uint32_t b, uint32_t c) {
    uint32_t d; asm("fma.rn.f16x2 %0,%1,%2,%3;" : "=r"(d) : "r"(a), "r"(b), "r"(c)); return d;
}
__device__ __forceinline__ uint32_t hmul2(uint32_t a, uint32_t b) {
    uint32_t d; asm("mul.rn.f16x2 %0,%1,%2;" : "=r"(d) : "r"(a), "r"(b)); return d;
}
__device__ __forceinline__ float2 cvt_f32x2(uint32_t p) {   // (lo, hi)
    float lo, hi;
    asm("{ .reg .f16 l, h; mov.b32 {l, h}, %2;"
        "  cvt.f32.f16 %0, l; cvt.f32.f16 %1, h; }"
        : "=f"(lo), "=f"(hi) : "r"(p));
    return make_float2(lo, hi);
}
__device__ __forceinline__ void mma16808(uint32_t d[2],
                                         uint32_t a0, uint32_t a1, uint32_t b,
                                         uint32_t c0, uint32_t c1)
{
    asm("mma.sync.aligned.m16n8k8.row.col.f16.f16.f16.f16 "
        "{%0,%1}, {%2,%3}, {%4}, {%5,%6};"
        : "=r"(d[0]), "=r"(d[1])
        : "r"(a0), "r"(a1), "r"(b), "r"(c0), "r"(c1));
}

__global__ __launch_bounds__(32)
void lstm_mma_kernel(const float* __restrict__ x,
                     const float* __restrict__ W_ih,
                     const float* __restrict__ W_hh,
                     const float* __restrict__ b_ih,
                     const float* __restrict__ b_hh,
                     const float* __restrict__ W_fc,
                     const float* __restrict__ b_fc,
                     float* __restrict__ out,
                     int B)
{
    const int lane = threadIdx.x & 31;
    const int grp  = lane >> 2;                     // batch row within chain / B n-index
    const int q    = lane & 3;                      // col-pair selector

    const int base = blockIdx.x * 16;               // 16 batches: chain A 0-7, chain B 8-15
    const int rA = base + grp;
    const int rB = base + 8 + grp;
    const bool vA = (rA < B), vB = (rB < B);
    const int rAc = vA ? rA : (B - 1);
    const int rBc = vB ? rB : (B - 1);

    // ---- B fragments per gate: scale = gate_scale * 0.5 (h' = 2h folding) ----
    uint32_t breg[4];
#pragma unroll
    for (int gt = 0; gt < 4; ++gt) {
        const float s = ((gt == 2) ? 1.0f : 0.5f) * 0.5f;
        const int row = gt * HDIM + grp;            // n = grp
        breg[gt] = cvt_f16x2(s * W_hh[row * HDIM + 2 * q + 1],
                             s * W_hh[row * HDIM + 2 * q]);
    }

    // ---- W_ih / bias in unit-pair f16x2 (lo = unit 2q, hi = 2q+1) ----
    uint32_t wih[4][IDIM], bias[4];
    {
        const int u0 = 2 * q, u1 = 2 * q + 1;
#pragma unroll
        for (int gt = 0; gt < 4; ++gt) {
            const float s = (gt == 2) ? 1.0f : 0.5f;
            const int ra = gt * HDIM + u0, rb = gt * HDIM + u1;
#pragma unroll
            for (int k = 0; k < IDIM; ++k)
                wih[gt][k] = cvt_f16x2(s * W_ih[rb * IDIM + k],
                                       s * W_ih[ra * IDIM + k]);
            bias[gt] = cvt_f16x2(s * (b_ih[rb] + b_hh[rb]),
                                 s * (b_ih[ra] + b_hh[ra]));
        }
    }

    const float4* __restrict__ xpA =
        reinterpret_cast<const float4*>(x) + (size_t)rAc * T_SEQ;
    const float4* __restrict__ xpB =
        reinterpret_cast<const float4*>(x) + (size_t)rBc * T_SEQ;

    const uint32_t K05 = 0x38003800u;               // (0.5, 0.5) half2

    // per-chain state: h' (=2h) as A fragment, c in f16x2
    uint32_t aA = 0u, cA = 0u;
    uint32_t aB = 0u, cB = 0u;

    auto ip_build = [&](const float4 xv, uint32_t (&ip)[4]) {
        const uint32_t d0 = cvt_f16x2(xv.x, xv.x), d1 = cvt_f16x2(xv.y, xv.y);
        const uint32_t d2 = cvt_f16x2(xv.z, xv.z), d3 = cvt_f16x2(xv.w, xv.w);
#pragma unroll
        for (int gt = 0; gt < 4; ++gt) {
            uint32_t p = hfma2(d0, wih[gt][0], bias[gt]);
            p = hfma2(d1, wih[gt][1], p);
            p = hfma2(d2, wih[gt][2], p);
            ip[gt] = hfma2(d3, wih[gt][3], p);
        }
    };

    // rolling 4-step x prefetch, both chains
    float4 bufA[4], bufB[4];
#pragma unroll
    for (int i = 0; i < 4; ++i) { bufA[i] = xpA[i]; bufB[i] = xpB[i]; }

    uint32_t ipA[4], ipB[4];
    ip_build(bufA[0], ipA);
    ip_build(bufB[0], ipB);

#pragma unroll 1
    for (int t0 = 0; t0 < T_SEQ; t0 += 4) {
        const int tn = (t0 + 4) & (T_SEQ - 1);
        float4 nA[4], nB[4];
#pragma unroll
        for (int i = 0; i < 4; ++i) { nA[i] = xpA[tn + i]; nB[i] = xpB[tn + i]; }

#pragma unroll
        for (int u = 0; u < 4; ++u) {
            // ---- 8 gate MMAs, both chains (independent; pipeline together) ----
            uint32_t dIA[2], dFA[2], dGA[2], dOA[2];
            uint32_t dIB[2], dFB[2], dGB[2], dOB[2];
            mma16808(dIA, aA, aA, breg[0], ipA[0], ipA[0]);
            mma16808(dIB, aB, aB, breg[0], ipB[0], ipB[0]);
            mma16808(dFA, aA, aA, breg[1], ipA[1], ipA[1]);
            mma16808(dFB, aB, aB, breg[1], ipB[1], ipB[1]);
            mma16808(dGA, aA, aA, breg[2], ipA[2], ipA[2]);
            mma16808(dGB, aB, aB, breg[2], ipB[2], ipB[2]);
            mma16808(dOA, aA, aA, breg[3], ipA[3], ipA[3]);
            mma16808(dOB, aB, aB, breg[3], ipB[3], ipB[3]);

            // ---- build IP(t+1) for both chains (off-chain work) ----
            uint32_t ipnA[4], ipnB[4];
            ip_build((u < 3) ? bufA[u + 1] : nA[0], ipnA);
            ip_build((u < 3) ? bufB[u + 1] : nB[0], ipnB);

            // ---- chain-A tail: c = 0.5*fma(tf,c,c) + 0.5*fma(ti,g,g); h' = fma(to,tc,tc)
            {
                const uint32_t tI = htanh2(dIA[0]);
                const uint32_t tF = htanh2(dFA[0]);
                const uint32_t tG = htanh2(dGA[0]);
                const uint32_t tO = htanh2(dOA[0]);
                const uint32_t fF = hfma2(tF, cA, cA);
                const uint32_t fI = hfma2(tI, tG, tG);
                cA = hfma2(fF, K05, hmul2(fI, K05));
                aA = hfma2(tO, htanh2(cA), htanh2(cA));
            }
            // ---- chain-B tail ----
            {
                const uint32_t tI = htanh2(dIB[0]);
                const uint32_t tF = htanh2(dFB[0]);
                const uint32_t tG = htanh2(dGB[0]);
                const uint32_t tO = htanh2(dOB[0]);
                const uint32_t fF = hfma2(tF, cB, cB);
                const uint32_t fI = hfma2(tI, tG, tG);
                cB = hfma2(fF, K05, hmul2(fI, K05));
                aB = hfma2(tO, htanh2(cB), htanh2(cB));
            }

#pragma unroll
            for (int gt = 0; gt < 4; ++gt) { ipA[gt] = ipnA[gt]; ipB[gt] = ipnB[gt]; }
        }

#pragma unroll
        for (int i = 0; i < 4; ++i) { bufA[i] = nA[i]; bufB[i] = nB[i]; }
    }

    // ---- FC head: h = h'/2 -> fold 0.5 into W_fc ----
    const float w0 = 0.5f * __ldg(W_fc + 2 * q);
    const float w1 = 0.5f * __ldg(W_fc + 2 * q + 1);
    const float2 hA = cvt_f32x2(aA);
    const float2 hB = cvt_f32x2(aB);
    float vAr = hA.x * w0 + hA.y * w1;
    float vBr = hB.x * w0 + hB.y * w1;
    vAr += __shfl_xor_sync(0xffffffffu, vAr, 1, 4);
    vAr += __shfl_xor_sync(0xffffffffu, vAr, 2, 4);
    vBr += __shfl_xor_sync(0xffffffffu, vBr, 1, 4);
    vBr += __shfl_xor_sync(0xffffffffu, vBr, 2, 4);

    if (q == 0) {
        const float bfc = __ldg(b_fc);
        if (vA) out[rA] = vAr + bfc;
        if (vB) out[rB] = vBr + bfc;
    }
}

extern "C" void kernel_launch(void* const* d_in, const int* in_sizes, int n_in,
                              void* d_out, int out_size)
{
    const float* x    = (const float*)d_in[0];
    const float* W_ih = (const float*)d_in[1];
    const float* W_hh = (const float*)d_in[2];
    const float* b_ih = (const float*)d_in[3];
    const float* b_hh = (const float*)d_in[4];
    const float* W_fc = (const float*)d_in[5];
    const float* b_fc = (const float*)d_in[6];
    float* out = (float*)d_out;

    const int B = in_sizes[0] / (T_SEQ * IDIM);     // 8192 here
    const int grid = (B + 15) / 16;                 // one warp per 16 batches (2 chains)

    lstm_mma_kernel<<<grid, 32>>>(x, W_ih, W_hh, b_ih, b_hh, W_fc, b_fc, out, B);
}